// round 4
// baseline (speedup 1.0000x reference)
#include <cuda_runtime.h>

// Problem constants
#define B_   16
#define CIN  8
#define COUT 32
#define DIN  48   // input D=H=W
#define DOUT 46   // output D=H=W (valid conv, k=3)
#define KVOL 216  // 8*3*3*3
#define HT   16   // output H rows per block (2 per thread)
#define TH   (HT + 2)   // input H rows per tile
#define TPB  384  // 8 row-pairs x 48 lanes = 12 warps = 3 per SMSP (even!)

#define NPOS_F   (46.f * 46.f * 46.f)
#define EPSGN    1e-5f

typedef unsigned long long u64;

__device__ float g_sums[B_ * 64];
__device__ float g_wT[KVOL * COUT];   // [k][oc]

// ---- packed fp32 helpers (fma.rn.f32x2) ----
__device__ __forceinline__ void ffma2(u64 &d, u64 a, u64 b) {
    asm("fma.rn.f32x2 %0, %1, %2, %0;" : "+l"(d) : "l"(a), "l"(b));
}
__device__ __forceinline__ u64 dup2(float x) {
    u64 r; asm("mov.b64 %0, {%1, %1};" : "=l"(r) : "f"(x)); return r;
}
__device__ __forceinline__ float2 unpack2(u64 v) {
    float2 f; asm("mov.b64 {%0, %1}, %2;" : "=f"(f.x), "=f"(f.y) : "l"(v)); return f;
}

// ---------------------------------------------------------------------------
// Prep: zero accumulators + transpose weights to [k][oc]
// ---------------------------------------------------------------------------
__global__ void prep_kernel(const float* __restrict__ w)
{
    int t = threadIdx.x;
    if (t < B_ * 64) g_sums[t] = 0.f;
    for (int i = t; i < KVOL * COUT; i += 1024) {
        int k = i >> 5, oc = i & 31;
        g_wT[i] = w[oc * KVOL + k];
    }
}

// ---------------------------------------------------------------------------
// Fused conv3d + bias + hardswish + per-channel sum / sum-sq
// grid = (3 h-chunks, 46 d, 16 b), block = 384
// Each thread: 2 adjacent h rows x 1 w x 32 channels (16 f32x2 pairs each)
// ---------------------------------------------------------------------------
extern __shared__ float smem[];

__global__ void __launch_bounds__(TPB)
conv_fused_kernel(const float* __restrict__ x,
                  const float* __restrict__ bias)
{
    float* x_s   = smem;                              // [8][3][TH][48]
    float* w_s   = smem + CIN * 3 * TH * DIN;         // [216][32]
    float* s_red = w_s + KVOL * COUT;                 // [64]
    float* b_s   = s_red + 64;                        // [32]

    const int b  = blockIdx.z;
    const int d0 = blockIdx.y;
    const int h0 = blockIdx.x * HT;
    const int tid = threadIdx.x;

    // --- weights: coalesced float4 copy ---
    {
        const float4* wg = (const float4*)g_wT;
        float4* ws4 = (float4*)w_s;
        for (int i = tid; i < KVOL * COUT / 4; i += TPB) ws4[i] = wg[i];
    }
    if (tid < 64) s_red[tid] = 0.f;
    if (tid < COUT) b_s[tid] = bias[tid];

    // --- input tile: 8 ch x 3 d x TH rows x 48 w (scalar, coalesced) ---
    for (int i = tid; i < CIN * 3 * TH * DIN; i += TPB) {
        int wq = i % DIN;
        int r  = i / DIN;
        int hh = r % TH;  r /= TH;
        int dz = r % 3;
        int ic = r / 3;
        int hg = h0 + hh;
        float v = 0.f;
        if (hg < DIN)
            v = x[(((b * CIN + ic) * DIN + (d0 + dz)) * DIN + hg) * DIN + wq];
        x_s[i] = v;
    }
    __syncthreads();

    const int wq = tid % DIN;        // 0..47
    const int hp = tid / DIN;        // 0..7 -> local rows 2hp, 2hp+1
    const bool vw = (wq < DOUT);
    const bool vA = vw && (h0 + 2 * hp     < DOUT);
    const bool vB = vw && (h0 + 2 * hp + 1 < DOUT);
    const int wc = min(wq, DOUT - 1);    // clamp: smem reads stay in-bounds

    u64 accA[16], accB[16];
    #pragma unroll
    for (int p = 0; p < 16; p++) { accA[p] = 0ull; accB[p] = 0ull; }

    #pragma unroll 1
    for (int ic = 0; ic < CIN; ic++) {
        #pragma unroll 1
        for (int kd = 0; kd < 3; kd++) {
            const float* xb = &x_s[((ic * 3 + kd) * TH + 2 * hp) * DIN + wc];
            const float* wb = &w_s[(ic * 3 + kd) * 9 * COUT];

            u64 dx[4][3];
            #pragma unroll
            for (int r = 0; r < 4; r++)
                #pragma unroll
                for (int t = 0; t < 3; t++)
                    dx[r][t] = dup2(xb[r * DIN + t]);

            #pragma unroll
            for (int kh = 0; kh < 3; kh++) {
                #pragma unroll
                for (int t = 0; t < 3; t++) {
                    u64 xa = dx[kh][t];
                    u64 xv = dx[kh + 1][t];
                    const ulonglong2* wp =
                        (const ulonglong2*)&wb[(kh * 3 + t) * COUT];
                    #pragma unroll
                    for (int j = 0; j < 8; j++) {
                        ulonglong2 W = wp[j];          // LDS.128 broadcast
                        ffma2(accA[2 * j],     W.x, xa);
                        ffma2(accA[2 * j + 1], W.y, xa);
                        ffma2(accB[2 * j],     W.x, xv);
                        ffma2(accB[2 * j + 1], W.y, xv);
                    }
                }
            }
        }
    }

    // --- bias + hardswish + warp reduce + block reduce (R2 epilogue) ---
    const unsigned lane = tid & 31;
    #pragma unroll
    for (int p = 0; p < 16; p++) {
        float2 a  = unpack2(accA[p]);
        float2 c2 = unpack2(accB[p]);
        #pragma unroll
        for (int q = 0; q < 2; q++) {
            int c = 2 * p + q;
            float ya = (q ? a.y : a.x) + b_s[c];
            float yb = (q ? c2.y : c2.x) + b_s[c];
            float ta = fminf(fmaxf(ya + 3.f, 0.f), 6.f);
            float tb = fminf(fmaxf(yb + 3.f, 0.f), 6.f);
            float va = vA ? ya * ta * (1.f / 6.f) : 0.f;
            float vb = vB ? yb * tb * (1.f / 6.f) : 0.f;
            float v  = va + vb;
            float v2 = va * va + vb * vb;
            #pragma unroll
            for (int off = 16; off; off >>= 1) {
                v  += __shfl_xor_sync(0xffffffffu, v,  off);
                v2 += __shfl_xor_sync(0xffffffffu, v2, off);
            }
            if (lane == 0) {
                atomicAdd(&s_red[c],      v);
                atomicAdd(&s_red[32 + c], v2);
            }
        }
    }
    __syncthreads();
    if (tid < 64) atomicAdd(&g_sums[b * 64 + tid], s_red[tid]);
}

// ---------------------------------------------------------------------------
// Finalize: GroupNorm stats from channel sums -> [B, C]
// ---------------------------------------------------------------------------
__global__ void finalize_kernel(const float* __restrict__ gn_w,
                                const float* __restrict__ gn_b,
                                float* __restrict__ out)
{
    int i = threadIdx.x;
    if (i >= B_ * COUT) return;
    int b = i >> 5, c = i & 31;
    int g = c >> 3;
    const float* s = &g_sums[b * 64];
    float S1 = 0.f, S2 = 0.f;
    #pragma unroll
    for (int j = 0; j < 8; j++) {
        S1 += s[g * 8 + j];
        S2 += s[32 + g * 8 + j];
    }
    float invNg = 1.f / (8.f * NPOS_F);
    float mean  = S1 * invNg;
    float var   = S2 * invNg - mean * mean;
    float rinv  = rsqrtf(var + EPSGN);
    float mc    = s[c] * (1.f / NPOS_F);
    out[i] = (mc - mean) * rinv * gn_w[c] + gn_b[c];
}

// ---------------------------------------------------------------------------
extern "C" void kernel_launch(void* const* d_in, const int* in_sizes, int n_in,
                              void* d_out, int out_size)
{
    const float* x      = (const float*)d_in[0];
    const float* weight = (const float*)d_in[1];
    const float* bias   = (const float*)d_in[2];
    const float* gn_w   = (const float*)d_in[3];
    const float* gn_b   = (const float*)d_in[4];
    float* out = (float*)d_out;

    const int smem_bytes =
        (CIN * 3 * TH * DIN + KVOL * COUT + 64 + COUT) * (int)sizeof(float);
    cudaFuncSetAttribute(conv_fused_kernel,
                         cudaFuncAttributeMaxDynamicSharedMemorySize, smem_bytes);

    prep_kernel<<<1, 1024>>>(weight);

    dim3 grid((DOUT + HT - 1) / HT, DOUT, B_);   // (3, 46, 16)
    conv_fused_kernel<<<grid, TPB, smem_bytes>>>(x, bias);

    finalize_kernel<<<1, 512>>>(gn_w, gn_b, out);
}

// round 5
// speedup vs baseline: 3.3722x; 3.3722x over previous
#include <cuda_runtime.h>

// Problem constants
#define B_    16
#define CIN   8
#define COUT  32
#define DIN   48
#define DOUT  46
#define HT    8      // output rows per block
#define THH   10     // input rows per tile (HT + 2)
#define XSTR  50     // x_s row stride (48 data + 2 zero pad)
#define WSTR  40     // w_s n stride (32 data + 8 pad -> conflict-free banks)
#define TPB   384    // 12 warps: (4 row-pairs) x (3 w-tiles)

#define NPOS_F (46.f * 46.f * 46.f)
#define EPSGN  1e-5f

__device__ float    g_sums[B_ * 64];
__device__ unsigned g_wB[CIN * 32 * WSTR];   // tf32 bits, [ic][j:32][40], j>=27 zero

__device__ __forceinline__ unsigned f2tf32(float f) {
    unsigned u; asm("cvt.rna.tf32.f32 %0, %1;" : "=r"(u) : "f"(f)); return u;
}

__device__ __forceinline__ void mma_tf32(float* c, const unsigned* a, const unsigned* b) {
    asm volatile(
        "mma.sync.aligned.m16n8k8.row.col.f32.tf32.tf32.f32 "
        "{%0,%1,%2,%3}, {%4,%5,%6,%7}, {%8,%9}, {%0,%1,%2,%3};"
        : "+f"(c[0]), "+f"(c[1]), "+f"(c[2]), "+f"(c[3])
        : "r"(a[0]), "r"(a[1]), "r"(a[2]), "r"(a[3]), "r"(b[0]), "r"(b[1]));
}

// ---------------------------------------------------------------------------
// Prep: zero accumulators + build padded tf32 weight tensor [ic][32][40]
// ---------------------------------------------------------------------------
__global__ void prep_kernel(const float* __restrict__ w)
{
    int t = threadIdx.x;
    if (t < B_ * 64) g_sums[t] = 0.f;
    for (int i = t; i < CIN * 32 * WSTR; i += 1024) {
        int n = i % WSTR;
        int r = i / WSTR;
        int j = r % 32;
        int ic = r / 32;
        unsigned val = 0u;
        if (j < 27 && n < COUT) {
            int kd = j / 9, r2 = j - 9 * kd;
            int kh = r2 / 3, kw = r2 - 3 * kh;
            val = f2tf32(w[(((n * CIN + ic) * 3 + kd) * 3 + kh) * 3 + kw]);
        }
        g_wB[i] = val;
    }
}

// ---------------------------------------------------------------------------
// Implicit-GEMM conv3d (tf32 mma.sync) + bias + hardswish + channel sums
// grid = (6 h-chunks, 46 d, 16 b), block = 384
// Per warp: M=32 positions (2 m-tiles: rows hp & hp+4, 16 w each), N=32, K=256
// ---------------------------------------------------------------------------
extern __shared__ float smem[];

__global__ void __launch_bounds__(TPB)
conv_mma_kernel(const float* __restrict__ x, const float* __restrict__ bias)
{
    unsigned* x_s = (unsigned*)smem;                        // 240*50 = 12000
    unsigned* w_s = (unsigned*)smem + 12000;                // 8*32*40 = 10240
    float* s_red  = smem + 12000 + 10240;                   // 64
    float* b_s    = s_red + 64;                             // 32

    const int b  = blockIdx.z;
    const int d0 = blockIdx.y;
    const int h0 = blockIdx.x * HT;
    const int tid = threadIdx.x;

    // --- weights: coalesced float4 copy (2560 float4) ---
    {
        const float4* src = (const float4*)g_wB;
        float4* dst = (float4*)w_s;
        #pragma unroll
        for (int i = 0; i < 7; i++) {
            int idx = tid + i * TPB;
            if (idx < CIN * 32 * WSTR / 4) dst[idx] = src[idx];
        }
    }
    if (tid < 64) s_red[tid] = 0.f;
    if (tid < COUT) b_s[tid] = bias[tid];

    // --- x tile: [8 ic][3 kd][10 rows][50 cols], tf32-converted, zero halo ---
    for (int i = tid; i < 240 * XSTR; i += TPB) {
        int col = i % XSTR;
        int r = i / XSTR;
        int ic = r / 30;
        int rem = r - ic * 30;
        int kd = rem / 10;
        int hh = rem - kd * 10;
        int hg = h0 + hh;
        float v = 0.f;
        if (hg < DIN && col < DIN)
            v = x[(((b * CIN + ic) * DIN + d0 + kd) * DIN + hg) * DIN + col];
        x_s[i] = f2tf32(v);
    }
    __syncthreads();

    const int wid  = tid >> 5, lane = tid & 31;
    const int grp  = lane >> 2, c = lane & 3;       // mma fragment coords
    const int wt   = wid % 3,  hp = wid / 3;        // w-tile, row-pair
    const int w0   = wt * 16;

    // per-thread im2col offsets: roff[q] for j = c + 4q (j>=27 -> 0, weight=0)
    int roff[8];
    #pragma unroll
    for (int q = 0; q < 8; q++) {
        int j = c + 4 * q;
        int o = 0;
        if (j < 27) {
            int kd = j / 9, r2 = j - 9 * kd;
            int kh = r2 / 3, kw = r2 - 3 * kh;
            o = (kd * THH + kh) * XSTR + kw;
        }
        roff[q] = o;
    }

    float acc[2][4][4];
    #pragma unroll
    for (int m = 0; m < 2; m++)
        #pragma unroll
        for (int n = 0; n < 4; n++)
            #pragma unroll
            for (int k = 0; k < 4; k++) acc[m][n][k] = 0.f;

    const int xbase0 = hp * XSTR + w0 + grp;        // + ic*1500 (+200 for mt1)
    const int wbase0 = c * WSTR + grp;              // + ic*1280 + cc*320 (+160 for j+4)

    #pragma unroll 2
    for (int ic = 0; ic < CIN; ic++) {
        const int xb = xbase0 + ic * (3 * THH * XSTR);   // 1500
        const int wb = wbase0 + ic * (32 * WSTR);        // 1280
        #pragma unroll
        for (int cc = 0; cc < 4; cc++) {
            unsigned bf[4][2];
            #pragma unroll
            for (int nt = 0; nt < 4; nt++) {
                bf[nt][0] = w_s[wb + cc * (8 * WSTR) + nt * 8];          // j = 8cc+c
                bf[nt][1] = w_s[wb + cc * (8 * WSTR) + 4 * WSTR + nt * 8]; // j+4
            }
            const int A1 = xb + roff[2 * cc];
            const int A2 = xb + roff[2 * cc + 1];
            unsigned af[2][4];
            #pragma unroll
            for (int mt = 0; mt < 2; mt++) {
                const int o = mt * (4 * XSTR);           // rows hp and hp+4
                af[mt][0] = x_s[A1 + o];
                af[mt][1] = x_s[A1 + o + 8];
                af[mt][2] = x_s[A2 + o];
                af[mt][3] = x_s[A2 + o + 8];
            }
            #pragma unroll
            for (int mt = 0; mt < 2; mt++)
                #pragma unroll
                for (int nt = 0; nt < 4; nt++)
                    mma_tf32(acc[mt][nt], af[mt], bf[nt]);
        }
    }

    // --- bias + hardswish + masked channel sums ---
    const bool vh[2] = { (h0 + hp) < DOUT, (h0 + hp + 4) < DOUT };
    const bool vw[2] = { (w0 + grp) < DOUT, (w0 + grp + 8) < DOUT };

    float sv[8], s2[8];
    #pragma unroll
    for (int i = 0; i < 8; i++) { sv[i] = 0.f; s2[i] = 0.f; }

    #pragma unroll
    for (int mt = 0; mt < 2; mt++) {
        #pragma unroll
        for (int half = 0; half < 2; half++) {
            const bool valid = vh[mt] && vw[half];
            #pragma unroll
            for (int nt = 0; nt < 4; nt++) {
                #pragma unroll
                for (int pr = 0; pr < 2; pr++) {
                    int ch = nt * 8 + 2 * c + pr;
                    float y = acc[mt][nt][half * 2 + pr] + b_s[ch];
                    float t = fminf(fmaxf(y + 3.f, 0.f), 6.f);
                    float v = valid ? y * t * (1.f / 6.f) : 0.f;
                    sv[nt * 2 + pr] += v;
                    s2[nt * 2 + pr] += v * v;
                }
            }
        }
    }

    // reduce across the 8 lanes sharing c (t%4): xor offsets 4, 8, 16
    #pragma unroll
    for (int i = 0; i < 8; i++) {
        #pragma unroll
        for (int off = 4; off <= 16; off <<= 1) {
            sv[i] += __shfl_xor_sync(0xffffffffu, sv[i], off);
            s2[i] += __shfl_xor_sync(0xffffffffu, s2[i], off);
        }
    }
    if (grp == 0) {       // lanes 0..3, lane c owns channels {8nt + 2c + pr}
        #pragma unroll
        for (int i = 0; i < 8; i++) {
            int ch = (i >> 1) * 8 + 2 * c + (i & 1);
            atomicAdd(&s_red[ch],      sv[i]);
            atomicAdd(&s_red[32 + ch], s2[i]);
        }
    }
    __syncthreads();
    if (tid < 64) atomicAdd(&g_sums[b * 64 + tid], s_red[tid]);
}

// ---------------------------------------------------------------------------
// Finalize: GroupNorm stats from channel sums -> [B, C]
// ---------------------------------------------------------------------------
__global__ void finalize_kernel(const float* __restrict__ gn_w,
                                const float* __restrict__ gn_b,
                                float* __restrict__ out)
{
    int i = threadIdx.x;
    if (i >= B_ * COUT) return;
    int b = i >> 5, c = i & 31;
    int g = c >> 3;
    const float* s = &g_sums[b * 64];
    float S1 = 0.f, S2 = 0.f;
    #pragma unroll
    for (int j = 0; j < 8; j++) {
        S1 += s[g * 8 + j];
        S2 += s[32 + g * 8 + j];
    }
    float invNg = 1.f / (8.f * NPOS_F);
    float mean  = S1 * invNg;
    float var   = S2 * invNg - mean * mean;
    float rinv  = rsqrtf(var + EPSGN);
    float mc    = s[c] * (1.f / NPOS_F);
    out[i] = (mc - mean) * rinv * gn_w[c] + gn_b[c];
}

// ---------------------------------------------------------------------------
extern "C" void kernel_launch(void* const* d_in, const int* in_sizes, int n_in,
                              void* d_out, int out_size)
{
    const float* x      = (const float*)d_in[0];
    const float* weight = (const float*)d_in[1];
    const float* bias   = (const float*)d_in[2];
    const float* gn_w   = (const float*)d_in[3];
    const float* gn_b   = (const float*)d_in[4];
    float* out = (float*)d_out;

    const int smem_bytes = (12000 + 10240 + 64 + 32) * (int)sizeof(float);
    cudaFuncSetAttribute(conv_mma_kernel,
                         cudaFuncAttributeMaxDynamicSharedMemorySize, smem_bytes);

    prep_kernel<<<1, 1024>>>(weight);

    dim3 grid((DOUT + HT - 1) / HT, DOUT, B_);   // (6, 46, 16)
    conv_mma_kernel<<<grid, TPB, smem_bytes>>>(x, bias);

    finalize_kernel<<<1, 512>>>(gn_w, gn_b, out);
}

// round 7
// speedup vs baseline: 3.4686x; 1.0286x over previous
#include <cuda_runtime.h>

// Problem constants
#define B_    16
#define CIN   8
#define COUT  32
#define DIN   48
#define DOUT  46
#define HT    8       // output h rows per block
#define THH   10      // input h rows per tile
#define XSTR  50      // x_s w stride (48 + 2 pad)
#define WSTR  40      // w_s n stride (32 + 8 pad, conflict-free)
#define KPP   56      // k-slots per ic-pair (54 real + 2 pad)
#define NCH   7       // k8 chunks per ic-pair
#define XPL   500     // plane stride in x_s (THH*XSTR)
#define XIC   2000    // ic stride in x_s (4 planes)
#define TPB   384     // 12 warps

#define NPOS_F (46.f * 46.f * 46.f)
#define EPSGN  1e-5f

__device__ float    g_sums[B_ * 64];
__device__ unsigned g_wB[4 * KPP * WSTR];   // tf32 bits [icpair][56][40]

__device__ __forceinline__ unsigned f2tf32(float f) {
    unsigned u; asm("cvt.rna.tf32.f32 %0, %1;" : "=r"(u) : "f"(f)); return u;
}

__device__ __forceinline__ void mma_tf32(float* c, const unsigned* a, const unsigned* b) {
    asm volatile(
        "mma.sync.aligned.m16n8k8.row.col.f32.tf32.tf32.f32 "
        "{%0,%1,%2,%3}, {%4,%5,%6,%7}, {%8,%9}, {%0,%1,%2,%3};"
        : "+f"(c[0]), "+f"(c[1]), "+f"(c[2]), "+f"(c[3])
        : "r"(a[0]), "r"(a[1]), "r"(a[2]), "r"(a[3]), "r"(b[0]), "r"(b[1]));
}

// ---------------------------------------------------------------------------
// Prep: zero accumulators + padded tf32 weights [icpair][j:56][n:40]
// j<54: icl=j/27, tap=j%27 -> ic = 2*icpair+icl, (kd,kh,kw)=tap
// ---------------------------------------------------------------------------
__global__ void prep_kernel(const float* __restrict__ w)
{
    int t = threadIdx.x;
    if (t < B_ * 64) g_sums[t] = 0.f;
    for (int i = t; i < 4 * KPP * WSTR; i += 1024) {
        int n = i % WSTR;
        int r = i / WSTR;
        int j = r % KPP;
        int p = r / KPP;
        unsigned val = 0u;
        if (j < 54 && n < COUT) {
            int icl = j / 27, tap = j - 27 * icl;
            int ic  = 2 * p + icl;
            int kd = tap / 9, r2 = tap - 9 * kd;
            int kh = r2 / 3, kw = r2 - 3 * kh;
            val = f2tf32(w[(((n * CIN + ic) * 3 + kd) * 3 + kh) * 3 + kw]);
        }
        g_wB[i] = val;
    }
}

// ---------------------------------------------------------------------------
// Implicit-GEMM conv3d (tf32 mma.sync), 2 d-outputs per block
// grid = (6 h-chunks, 23 d-pairs, 16 b), block = 384
// ---------------------------------------------------------------------------
extern __shared__ float smem[];

__global__ void __launch_bounds__(TPB)
conv_mma_kernel(const float* __restrict__ x, const float* __restrict__ bias)
{
    unsigned* x_s = (unsigned*)smem;                 // [8 ic][4 planes][10][50] = 16000
    unsigned* w_s = (unsigned*)smem + 16000;         // 4*56*40 = 8960
    float* s_red  = smem + 16000 + 8960;             // 64
    float* b_s    = s_red + 64;                      // 32

    const int b   = blockIdx.z;
    const int db  = blockIdx.y;          // d-pair: outputs 2db, 2db+1
    const int h0  = blockIdx.x * HT;
    const int tid = threadIdx.x;

    // --- weights: coalesced float4 copy (2240 float4) ---
    {
        const float4* src = (const float4*)g_wB;
        float4* dst = (float4*)w_s;
        for (int i = tid; i < 4 * KPP * WSTR / 4; i += TPB) dst[i] = src[i];
    }
    if (tid < 64) s_red[tid] = 0.f;
    if (tid < COUT) b_s[tid] = bias[tid];

    // --- x tile: [8 ic][4 planes][10 rows][50 cols], tf32, zero halo ---
    for (int i = tid; i < CIN * 4 * THH * XSTR; i += TPB) {
        int col = i % XSTR;
        int r   = i / XSTR;
        int hh  = r % THH;
        int r2  = r / THH;
        int kd4 = r2 & 3;
        int ic  = r2 >> 2;
        int hg  = h0 + hh;
        int dg  = 2 * db + kd4;          // <= 47, always in-bounds
        float v = 0.f;
        if (hg < DIN && col < DIN)
            v = x[(((b * CIN + ic) * DIN + dg) * DIN + hg) * DIN + col];
        x_s[i] = f2tf32(v);
    }
    __syncthreads();

    const int wid  = tid >> 5, lane = tid & 31;
    const int grp  = lane >> 2, c = lane & 3;
    const int wt   = wid % 3,  hp = wid / 3;       // w-tile (16 wide), row-pair
    const int w0   = wt * 16;

    // im2col offsets: for chunk cc, k-slots j = 8cc + c and 8cc + c + 4
    int roff[NCH][2];
    #pragma unroll
    for (int cc = 0; cc < NCH; cc++) {
        #pragma unroll
        for (int s = 0; s < 2; s++) {
            int jj = 8 * cc + c + 4 * s;
            int o = 0;
            if (jj < 54) {
                int icl = jj / 27, tap = jj - 27 * icl;
                int kd = tap / 9, r2 = tap - 9 * kd;
                int kh = r2 / 3, kw = r2 - 3 * kh;
                o = icl * XIC + kd * XPL + kh * XSTR + kw;
            }
            roff[cc][s] = o;
        }
    }

    const bool vh[2] = { true, (h0 + hp + 4) < DOUT };   // hp<=3: row1 always valid
    const bool vw[2] = { (w0 + grp) < DOUT, (w0 + grp + 8) < DOUT };

    float sv[8], s2[8];
    #pragma unroll
    for (int i = 0; i < 8; i++) { sv[i] = 0.f; s2[i] = 0.f; }

    #pragma unroll 1
    for (int dd = 0; dd < 2; dd++) {
        float acc[2][4][4];
        #pragma unroll
        for (int m = 0; m < 2; m++)
            #pragma unroll
            for (int n = 0; n < 4; n++)
                #pragma unroll
                for (int k = 0; k < 4; k++) acc[m][n][k] = 0.f;

        const int xbase = dd * XPL + hp * XSTR + w0 + grp;

        #pragma unroll 1
        for (int p = 0; p < 4; p++) {
            const int xb = xbase + p * (2 * XIC);     // ic pair base (4000)
            const int wb = p * (KPP * WSTR) + c * WSTR + grp;
            #pragma unroll
            for (int cc = 0; cc < NCH; cc++) {
                unsigned bf[4][2];
                #pragma unroll
                for (int nt = 0; nt < 4; nt++) {
                    bf[nt][0] = w_s[wb + (8 * cc)     * WSTR + nt * 8];
                    bf[nt][1] = w_s[wb + (8 * cc + 4) * WSTR + nt * 8];
                }
                const int A1 = xb + roff[cc][0];
                const int A2 = xb + roff[cc][1];
                unsigned af[2][4];
                #pragma unroll
                for (int mt = 0; mt < 2; mt++) {
                    const int o = mt * (4 * XSTR);    // rows hp, hp+4
                    af[mt][0] = x_s[A1 + o];
                    af[mt][1] = x_s[A1 + o + 8];
                    af[mt][2] = x_s[A2 + o];
                    af[mt][3] = x_s[A2 + o + 8];
                }
                #pragma unroll
                for (int mt = 0; mt < 2; mt++)
                    #pragma unroll
                    for (int nt = 0; nt < 4; nt++)
                        mma_tf32(acc[mt][nt], af[mt], bf[nt]);
            }
        }

        // --- bias + hardswish + masked accumulate (d rows always valid) ---
        #pragma unroll
        for (int mt = 0; mt < 2; mt++) {
            #pragma unroll
            for (int half = 0; half < 2; half++) {
                const bool valid = vh[mt] && vw[half];
                #pragma unroll
                for (int nt = 0; nt < 4; nt++) {
                    #pragma unroll
                    for (int pr = 0; pr < 2; pr++) {
                        int ch = nt * 8 + 2 * c + pr;
                        float y = acc[mt][nt][half * 2 + pr] + b_s[ch];
                        float t = fminf(fmaxf(y + 3.f, 0.f), 6.f);
                        float v = valid ? y * t * (1.f / 6.f) : 0.f;
                        sv[nt * 2 + pr] += v;
                        s2[nt * 2 + pr] += v * v;
                    }
                }
            }
        }
    }

    // reduce across the 8 lanes sharing c: xor 4, 8, 16
    #pragma unroll
    for (int i = 0; i < 8; i++) {
        #pragma unroll
        for (int off = 4; off <= 16; off <<= 1) {
            sv[i] += __shfl_xor_sync(0xffffffffu, sv[i], off);
            s2[i] += __shfl_xor_sync(0xffffffffu, s2[i], off);
        }
    }
    if (grp == 0) {
        #pragma unroll
        for (int i = 0; i < 8; i++) {
            int ch = (i >> 1) * 8 + 2 * c + (i & 1);
            atomicAdd(&s_red[ch],      sv[i]);
            atomicAdd(&s_red[32 + ch], s2[i]);
        }
    }
    __syncthreads();
    if (tid < 64) atomicAdd(&g_sums[b * 64 + tid], s_red[tid]);
}

// ---------------------------------------------------------------------------
// Finalize: GroupNorm stats from channel sums -> [B, C]
// ---------------------------------------------------------------------------
__global__ void finalize_kernel(const float* __restrict__ gn_w,
                                const float* __restrict__ gn_b,
                                float* __restrict__ out)
{
    int i = threadIdx.x;
    if (i >= B_ * COUT) return;
    int b = i >> 5, c = i & 31;
    int g = c >> 3;
    const float* s = &g_sums[b * 64];
    float S1 = 0.f, S2 = 0.f;
    #pragma unroll
    for (int j = 0; j < 8; j++) {
        S1 += s[g * 8 + j];
        S2 += s[32 + g * 8 + j];
    }
    float invNg = 1.f / (8.f * NPOS_F);
    float mean  = S1 * invNg;
    float var   = S2 * invNg - mean * mean;
    float rinv  = rsqrtf(var + EPSGN);
    float mc    = s[c] * (1.f / NPOS_F);
    out[i] = (mc - mean) * rinv * gn_w[c] + gn_b[c];
}

// ---------------------------------------------------------------------------
extern "C" void kernel_launch(void* const* d_in, const int* in_sizes, int n_in,
                              void* d_out, int out_size)
{
    const float* x      = (const float*)d_in[0];
    const float* weight = (const float*)d_in[1];
    const float* bias   = (const float*)d_in[2];
    const float* gn_w   = (const float*)d_in[3];
    const float* gn_b   = (const float*)d_in[4];
    float* out = (float*)d_out;

    const int smem_bytes = (16000 + 8960 + 64 + 32) * (int)sizeof(float);
    cudaFuncSetAttribute(conv_mma_kernel,
                         cudaFuncAttributeMaxDynamicSharedMemorySize, smem_bytes);

    prep_kernel<<<1, 1024>>>(weight);

    dim3 grid(6, 23, B_);
    conv_mma_kernel<<<grid, TPB, smem_bytes>>>(x, bias);

    finalize_kernel<<<1, 512>>>(gn_w, gn_b, out);
}